// round 1
// baseline (speedup 1.0000x reference)
#include <cuda_runtime.h>
#include <cuda_bf16.h>

#define NNODES 50000
#define NEDGES 800000
#define DIM    128
#define NLAYER 5
#define NGRAPH 1000

// Scratch (no allocation allowed)
__device__ float g_h[NNODES * DIM];
__device__ float g_aggr[NNODES * DIM];
__device__ float g_z[NNODES * DIM];
__device__ float g_gsum[NGRAPH];
__device__ int   g_gcnt[NGRAPH];

// ---------------------------------------------------------------------------
// Vector copy: dst = src  (N float4 elements)
// ---------------------------------------------------------------------------
__global__ void veccopy_kernel(float4* __restrict__ dst, const float4* __restrict__ src, int n4) {
    int i = blockIdx.x * blockDim.x + threadIdx.x;
    if (i < n4) dst[i] = src[i];
}

// ---------------------------------------------------------------------------
// Edge scatter: aggr[dst] += h[src]   (one warp per edge, float4 per lane)
// ---------------------------------------------------------------------------
__global__ void scatter_kernel(const int* __restrict__ src_idx,
                               const int* __restrict__ dst_idx,
                               const float* __restrict__ h,
                               float* __restrict__ aggr) {
    int warp = (blockIdx.x * blockDim.x + threadIdx.x) >> 5;
    int lane = threadIdx.x & 31;
    if (warp >= NEDGES) return;
    int s = src_idx[warp];
    int d = dst_idx[warp];
    const float4* hp = reinterpret_cast<const float4*>(h + (size_t)s * DIM);
    float4 v = hp[lane];
    float4* ap = reinterpret_cast<float4*>(aggr + (size_t)d * DIM) + lane;
    asm volatile("red.global.add.v4.f32 [%0], {%1, %2, %3, %4};"
                 :: "l"(ap), "f"(v.x), "f"(v.y), "f"(v.z), "f"(v.w)
                 : "memory");
}

// ---------------------------------------------------------------------------
// GEMM: C[m][n] = relu(sum_k A[m][k] * W[k][n] + bias[n])
// M x 128 @ 128 x 128, BM=64 rows per block, full K and N resident in SMEM.
// 256 threads: tx = t%16 (8 cols each), ty = t/16 (4 rows each).
// ---------------------------------------------------------------------------
#define GEMM_BM 64
#define AS_STRIDE 132   // padded row stride (floats), div by 4, kills bank conflicts
#define GEMM_SMEM ((GEMM_BM * AS_STRIDE + 128 * 128) * 4)

__global__ __launch_bounds__(256) void gin_gemm_kernel(
    const float* __restrict__ A, const float* __restrict__ W,
    const float* __restrict__ bias, float* __restrict__ C, int M)
{
    extern __shared__ float sm[];
    float* As = sm;                        // [64][AS_STRIDE]
    float* Ws = sm + GEMM_BM * AS_STRIDE;  // [128][128]

    int t = threadIdx.x;
    int m0 = blockIdx.x * GEMM_BM;
    int maxr = M - m0;

    // Load W (128x128 = 4096 float4, 16 per thread), coalesced
    const float4* W4 = reinterpret_cast<const float4*>(W);
    float4* Ws4 = reinterpret_cast<float4*>(Ws);
#pragma unroll
    for (int i = 0; i < 16; i++) Ws4[t + i * 256] = W4[t + i * 256];

    // Load A tile (64x128 = 2048 float4, 8 per thread), coalesced, padded rows
    const float4* A4 = reinterpret_cast<const float4*>(A + (size_t)m0 * DIM);
#pragma unroll
    for (int i = 0; i < 8; i++) {
        int idx = t + i * 256;           // float4 index within tile
        int r = idx >> 5;                // row (32 float4 per row)
        int kq = idx & 31;
        float4 v = (r < maxr) ? A4[idx] : make_float4(0.f, 0.f, 0.f, 0.f);
        *reinterpret_cast<float4*>(As + r * AS_STRIDE + kq * 4) = v;
    }
    __syncthreads();

    int tx = t & 15;       // column group: cols [tx*8, tx*8+8)
    int ty = t >> 4;       // row group: rows [ty*4, ty*4+4)
    int cn = tx * 8;
    int rm = ty * 4;

    float acc[4][8];
#pragma unroll
    for (int i = 0; i < 4; i++)
#pragma unroll
        for (int j = 0; j < 8; j++) acc[i][j] = 0.f;

#pragma unroll 8
    for (int k = 0; k < 128; k++) {
        float a0 = As[(rm + 0) * AS_STRIDE + k];
        float a1 = As[(rm + 1) * AS_STRIDE + k];
        float a2 = As[(rm + 2) * AS_STRIDE + k];
        float a3 = As[(rm + 3) * AS_STRIDE + k];
        float4 w0 = *reinterpret_cast<const float4*>(Ws + k * 128 + cn);
        float4 w1 = *reinterpret_cast<const float4*>(Ws + k * 128 + cn + 4);
        float w[8] = {w0.x, w0.y, w0.z, w0.w, w1.x, w1.y, w1.z, w1.w};
#pragma unroll
        for (int j = 0; j < 8; j++) {
            acc[0][j] = fmaf(a0, w[j], acc[0][j]);
            acc[1][j] = fmaf(a1, w[j], acc[1][j]);
            acc[2][j] = fmaf(a2, w[j], acc[2][j]);
            acc[3][j] = fmaf(a3, w[j], acc[3][j]);
        }
    }

    float4 bb0 = *reinterpret_cast<const float4*>(bias + cn);
    float4 bb1 = *reinterpret_cast<const float4*>(bias + cn + 4);
    float bb[8] = {bb0.x, bb0.y, bb0.z, bb0.w, bb1.x, bb1.y, bb1.z, bb1.w};

#pragma unroll
    for (int i = 0; i < 4; i++) {
        int row = rm + i;
        if (row < maxr) {
            float4 o0, o1;
            o0.x = fmaxf(acc[i][0] + bb[0], 0.f);
            o0.y = fmaxf(acc[i][1] + bb[1], 0.f);
            o0.z = fmaxf(acc[i][2] + bb[2], 0.f);
            o0.w = fmaxf(acc[i][3] + bb[3], 0.f);
            o1.x = fmaxf(acc[i][4] + bb[4], 0.f);
            o1.y = fmaxf(acc[i][5] + bb[5], 0.f);
            o1.z = fmaxf(acc[i][6] + bb[6], 0.f);
            o1.w = fmaxf(acc[i][7] + bb[7], 0.f);
            float* cp = C + (size_t)(m0 + row) * DIM + cn;
            *reinterpret_cast<float4*>(cp) = o0;
            *reinterpret_cast<float4*>(cp + 4) = o1;
        }
    }
}

// ---------------------------------------------------------------------------
// Pooling: per node compute s = dot(h[n], Wh), accumulate into its graph.
// pooled @ Wh == (sum_n in g of h[n]@Wh) / cnt_g
// ---------------------------------------------------------------------------
__global__ void pool_kernel(const float* __restrict__ h,
                            const int* __restrict__ batch,
                            const float* __restrict__ Wh,
                            float* __restrict__ gsum, int* __restrict__ gcnt) {
    int warp = (blockIdx.x * blockDim.x + threadIdx.x) >> 5;
    int lane = threadIdx.x & 31;
    if (warp >= NNODES) return;
    float4 v = reinterpret_cast<const float4*>(h + (size_t)warp * DIM)[lane];
    float4 w = reinterpret_cast<const float4*>(Wh)[lane];
    float s = v.x * w.x + v.y * w.y + v.z * w.z + v.w * w.w;
#pragma unroll
    for (int off = 16; off > 0; off >>= 1)
        s += __shfl_xor_sync(0xFFFFFFFF, s, off);
    if (lane == 0) {
        int g = batch[warp];
        atomicAdd(&gsum[g], s);
        atomicAdd(&gcnt[g], 1);
    }
}

__global__ void finalize_kernel(const float* __restrict__ gsum,
                                const int* __restrict__ gcnt,
                                const float* __restrict__ bh,
                                float* __restrict__ out) {
    int g = blockIdx.x * blockDim.x + threadIdx.x;
    if (g < NGRAPH) {
        float c = (float)gcnt[g];
        out[g] = gsum[g] / fmaxf(c, 1.0f) + bh[0];
    }
}

// ---------------------------------------------------------------------------
extern "C" void kernel_launch(void* const* d_in, const int* in_sizes, int n_in,
                              void* d_out, int out_size) {
    const float* x     = (const float*)d_in[0];
    const int*   ei    = (const int*)d_in[1];   // [2, E]: src = ei, dst = ei+E
    const int*   batch = (const int*)d_in[2];
    const float* W1s   = (const float*)d_in[3];
    const float* b1s   = (const float*)d_in[4];
    const float* W2s   = (const float*)d_in[5];
    const float* b2s   = (const float*)d_in[6];
    const float* Wh    = (const float*)d_in[7];
    const float* bh    = (const float*)d_in[8];
    float* out = (float*)d_out;

    float *h, *aggr, *z, *gsum;
    int* gcnt;
    cudaGetSymbolAddress((void**)&h,    g_h);
    cudaGetSymbolAddress((void**)&aggr, g_aggr);
    cudaGetSymbolAddress((void**)&z,    g_z);
    cudaGetSymbolAddress((void**)&gsum, g_gsum);
    cudaGetSymbolAddress((void**)&gcnt, g_gcnt);

    cudaFuncSetAttribute(gin_gemm_kernel,
                         cudaFuncAttributeMaxDynamicSharedMemorySize, GEMM_SMEM);

    const int n4 = NNODES * DIM / 4;           // 1.6M float4
    const int copy_blocks = (n4 + 255) / 256;
    const int scatter_blocks = (NEDGES * 32 + 255) / 256;
    const int gemm_blocks = (NNODES + GEMM_BM - 1) / GEMM_BM;
    const int pool_blocks = (NNODES * 32 + 255) / 256;

    // h = x
    veccopy_kernel<<<copy_blocks, 256>>>((float4*)h, (const float4*)x, n4);

    for (int l = 0; l < NLAYER; l++) {
        // aggr = h  (fuse the "+h" of GIN eps=0 into the scatter init)
        veccopy_kernel<<<copy_blocks, 256>>>((float4*)aggr, (const float4*)h, n4);
        // aggr[dst] += h[src]
        scatter_kernel<<<scatter_blocks, 256>>>(ei, ei + NEDGES, h, aggr);
        // z = relu(aggr @ W1 + b1)
        gin_gemm_kernel<<<gemm_blocks, 256, GEMM_SMEM>>>(
            aggr, W1s + (size_t)l * DIM * DIM, b1s + (size_t)l * DIM, z, NNODES);
        // h = relu(z @ W2 + b2)   (outer relu of the layer)
        gin_gemm_kernel<<<gemm_blocks, 256, GEMM_SMEM>>>(
            z, W2s + (size_t)l * DIM * DIM, b2s + (size_t)l * DIM, h, NNODES);
    }

    cudaMemsetAsync(gsum, 0, NGRAPH * sizeof(float));
    cudaMemsetAsync(gcnt, 0, NGRAPH * sizeof(int));
    pool_kernel<<<pool_blocks, 256>>>(h, batch, Wh, gsum, gcnt);
    finalize_kernel<<<(NGRAPH + 255) / 256, 256>>>(gsum, gcnt, bh, out);
}

// round 10
// speedup vs baseline: 1.7762x; 1.7762x over previous
#include <cuda_runtime.h>
#include <cuda_bf16.h>
#include <cstdint>

#define NNODES 50000
#define NEDGES 800000
#define DIM    128
#define NLAYER 5
#define NGRAPH 1000
#define TILE_M 128
#define NTILES ((NNODES + TILE_M - 1) / TILE_M)

// ---------------------------------------------------------------------------
// Scratch (no allocation allowed)
// ---------------------------------------------------------------------------
__device__ float g_h[NNODES * DIM];
__device__ float g_aggr[NNODES * DIM];
__device__ __nv_bfloat16 g_wimg[NLAYER * 4 * DIM * DIM];  // per layer: W1hi,W1lo,W2hi,W2lo (W^T, [n][k])
__device__ float g_gsum[NGRAPH];
__device__ int   g_gcnt[NGRAPH];

// ---------------------------------------------------------------------------
// helpers
// ---------------------------------------------------------------------------
__device__ __forceinline__ uint32_t smem_u32(const void* p) {
    uint32_t a;
    asm("{ .reg .u64 t; cvta.to.shared.u64 t, %1; cvt.u32.u64 %0, t; }" : "=r"(a) : "l"(p));
    return a;
}
__device__ __forceinline__ uint32_t pack2bf(float a, float b) {
    __nv_bfloat162 t = __floats2bfloat162_rn(a, b);
    return *reinterpret_cast<uint32_t*>(&t);
}

#define LDSM_X4(r0, r1, r2, r3, addr) \
    asm volatile("ldmatrix.sync.aligned.m8n8.x4.shared.b16 {%0,%1,%2,%3}, [%4];" \
                 : "=r"(r0), "=r"(r1), "=r"(r2), "=r"(r3) : "r"(addr))

#define MMA_BF16(d, a, b) \
    asm volatile("mma.sync.aligned.m16n8k16.row.col.f32.bf16.bf16.f32 " \
                 "{%0,%1,%2,%3}, {%4,%5,%6,%7}, {%8,%9}, {%0,%1,%2,%3};" \
                 : "+f"((d)[0]), "+f"((d)[1]), "+f"((d)[2]), "+f"((d)[3]) \
                 : "r"((a)[0]), "r"((a)[1]), "r"((a)[2]), "r"((a)[3]), \
                   "r"((b)[0]), "r"((b)[1]))

// uint32 offsets of the four per-layer weight images (image = DIM*DIM bf16 = 8192 u32)
#define WIMG_U32 8192
#define OFF_W1HI 0
#define OFF_W1LO (1 * WIMG_U32)
#define OFF_W2HI (2 * WIMG_U32)
#define OFF_W2LO (3 * WIMG_U32)

// ---------------------------------------------------------------------------
// Prep: split W (fp32, [L][K][N]) into transposed bf16 hi/lo images, [n][k]
// dense layout. Image index: l*4 + m*2 + part.
// ---------------------------------------------------------------------------
__global__ void prep_w_kernel(const float* __restrict__ W1s, const float* __restrict__ W2s) {
    int idx = blockIdx.x * blockDim.x + threadIdx.x;
    if (idx >= NLAYER * 2 * DIM * DIM) return;
    int l = idx / (2 * DIM * DIM);
    int rem = idx % (2 * DIM * DIM);
    int m = rem / (DIM * DIM);
    int kn = rem % (DIM * DIM);
    int k = kn / DIM, n = kn % DIM;
    float w = (m == 0 ? W1s : W2s)[(size_t)l * DIM * DIM + k * DIM + n];
    __nv_bfloat16 hi = __float2bfloat16_rn(w);
    __nv_bfloat16 lo = __float2bfloat16_rn(w - __bfloat162float(hi));
    __nv_bfloat16* base = g_wimg + (size_t)(l * 4 + m * 2) * DIM * DIM;
    base[n * DIM + k] = hi;                 // W^T: row n, col k
    base[DIM * DIM + n * DIM + k] = lo;
}

// ---------------------------------------------------------------------------
// Edge scatter: aggr[dst] += h[src]   (one warp per edge, float4 per lane)
// ---------------------------------------------------------------------------
__global__ void scatter_kernel(const int* __restrict__ src_idx,
                               const int* __restrict__ dst_idx,
                               const float* __restrict__ h,
                               float* __restrict__ aggr) {
    int warp = (blockIdx.x * blockDim.x + threadIdx.x) >> 5;
    int lane = threadIdx.x & 31;
    if (warp >= NEDGES) return;
    int s = src_idx[warp];
    int d = dst_idx[warp];
    float4 v = reinterpret_cast<const float4*>(h + (size_t)s * DIM)[lane];
    float4* ap = reinterpret_cast<float4*>(aggr + (size_t)d * DIM) + lane;
    asm volatile("red.global.add.v4.f32 [%0], {%1, %2, %3, %4};"
                 :: "l"(ap), "f"(v.x), "f"(v.y), "f"(v.z), "f"(v.w) : "memory");
}

// ---------------------------------------------------------------------------
// Fused GIN MLP: out = relu(relu((in+aggr) @ W1 + b1) @ W2 + b2)
// One CTA per 128 rows; warp mma.sync bf16 hi/lo split; K=128 resident.
// SMEM tiles padded to stride 136 bf16 (= 17 x 16B) -> ldmatrix conflict-free.
// ---------------------------------------------------------------------------
#define ASTRIDE 136                       // bf16 units per row
#define TILE_BYTES (128 * ASTRIDE * 2)    // 34816
#define SM_AHI 0
#define SM_ALO (SM_AHI + TILE_BYTES)
#define SM_WHI (SM_ALO + TILE_BYTES)
#define SM_WLO (SM_WHI + TILE_BYTES)
#define SM_B1  (SM_WLO + TILE_BYTES)      // 139264
#define SM_B2  (SM_B1 + 512)
#define SM_TOTAL (SM_B2 + 512)

__global__ __launch_bounds__(256, 1) void gin_mlp_kernel(
    const float* __restrict__ in, const float* __restrict__ aggr,
    const __nv_bfloat16* __restrict__ wimg,
    const float* __restrict__ b1, const float* __restrict__ b2,
    float* __restrict__ out, int M)
{
    extern __shared__ char smem[];
    uint32_t sb = smem_u32(smem);
    int tid = threadIdx.x;
    int wid = tid >> 5;
    int lane = tid & 31;
    int m0 = blockIdx.x * TILE_M;
    int maxr = M - m0;

    // bias -> smem
    if (tid < DIM) {
        *reinterpret_cast<float*>(smem + SM_B1 + tid * 4) = b1[tid];
        *reinterpret_cast<float*>(smem + SM_B2 + tid * 4) = b2[tid];
    }

    // ---- W1 hi/lo -> smem (dense gmem -> padded smem), as uint32 pairs ----
    {
        const uint32_t* wg = reinterpret_cast<const uint32_t*>(wimg);
        uint32_t* wh = reinterpret_cast<uint32_t*>(smem + SM_WHI);
        uint32_t* wl = reinterpret_cast<uint32_t*>(smem + SM_WLO);
#pragma unroll
        for (int i = 0; i < 32; i++) {
            int idx = tid + i * 256;         // uint32 index in 128x64 grid
            int r = idx >> 6, c2 = idx & 63;
            wh[r * 68 + c2] = wg[OFF_W1HI + idx];
            wl[r * 68 + c2] = wg[OFF_W1LO + idx];
        }
    }

    // ---- A tile: (in + aggr) -> bf16 hi/lo, padded smem ----
    {
        const float4* in4 = reinterpret_cast<const float4*>(in + (size_t)m0 * DIM);
        const float4* ag4 = reinterpret_cast<const float4*>(aggr + (size_t)m0 * DIM);
#pragma unroll
        for (int i = 0; i < 16; i++) {
            int f = tid + i * 256;           // float4 index in 128x32 grid
            int r = f >> 5, c4 = f & 31;
            float4 a = make_float4(0.f, 0.f, 0.f, 0.f);
            if (r < maxr) {
                float4 x = in4[f], g = ag4[f];
                a.x = x.x + g.x; a.y = x.y + g.y; a.z = x.z + g.z; a.w = x.w + g.w;
            }
            __nv_bfloat16 h0 = __float2bfloat16_rn(a.x), h1 = __float2bfloat16_rn(a.y);
            __nv_bfloat16 h2 = __float2bfloat16_rn(a.z), h3 = __float2bfloat16_rn(a.w);
            uint32_t u32i = (uint32_t)(r * 68 + c4 * 2);
            reinterpret_cast<uint2*>(smem + SM_AHI)[u32i >> 1] =
                make_uint2(pack2bf(__bfloat162float(h0), __bfloat162float(h1)),
                           pack2bf(__bfloat162float(h2), __bfloat162float(h3)));
            reinterpret_cast<uint2*>(smem + SM_ALO)[u32i >> 1] =
                make_uint2(pack2bf(a.x - __bfloat162float(h0), a.y - __bfloat162float(h1)),
                           pack2bf(a.z - __bfloat162float(h2), a.w - __bfloat162float(h3)));
        }
    }
    __syncthreads();

    // warp tiling: 4 warps along M x 2 along N
    int wm = (wid & 3) * 32;       // warp row base
    int wn = (wid >> 2) * 64;      // warp col base

    // ldmatrix source addresses (byte offsets within a tile):
    // A (x4): thread i -> row (i%16), k-half (i/16)
    uint32_t a_off = (uint32_t)(((lane & 15) * ASTRIDE) * 2 + (lane >> 4) * 16);
    // B (x4, two n-tiles): thread i -> row ((i/16)*8 + (i&7)), k-half ((i>>3)&1)
    uint32_t b_off = (uint32_t)((((lane >> 4) * 8 + (lane & 7)) * ASTRIDE) * 2 + ((lane >> 3) & 1) * 16);

    float d[2][8][4];
    uint32_t qr = lane >> 2, qc = lane & 3;

    const float* bias_s[2] = { reinterpret_cast<const float*>(smem + SM_B1),
                               reinterpret_cast<const float*>(smem + SM_B2) };

#pragma unroll 1
    for (int phase = 0; phase < 2; phase++) {
#pragma unroll
        for (int mt = 0; mt < 2; mt++)
#pragma unroll
            for (int nt = 0; nt < 8; nt++)
#pragma unroll
                for (int r = 0; r < 4; r++) d[mt][nt][r] = 0.f;

#pragma unroll
        for (int ks = 0; ks < 8; ks++) {
            uint32_t kbyte = (uint32_t)(ks * 32);
            uint32_t ah[2][4], al[2][4], bh[8][2], bl[8][2];
#pragma unroll
            for (int mt = 0; mt < 2; mt++) {
                uint32_t row = (uint32_t)((wm + mt * 16) * ASTRIDE * 2);
                LDSM_X4(ah[mt][0], ah[mt][1], ah[mt][2], ah[mt][3], sb + SM_AHI + row + a_off + kbyte);
                LDSM_X4(al[mt][0], al[mt][1], al[mt][2], al[mt][3], sb + SM_ALO + row + a_off + kbyte);
            }
#pragma unroll
            for (int np = 0; np < 4; np++) {
                uint32_t row = (uint32_t)((wn + np * 16) * ASTRIDE * 2);
                LDSM_X4(bh[np*2][0], bh[np*2][1], bh[np*2+1][0], bh[np*2+1][1], sb + SM_WHI + row + b_off + kbyte);
                LDSM_X4(bl[np*2][0], bl[np*2][1], bl[np*2+1][0], bl[np*2+1][1], sb + SM_WLO + row + b_off + kbyte);
            }
#pragma unroll
            for (int mt = 0; mt < 2; mt++)
#pragma unroll
                for (int nt = 0; nt < 8; nt++) {
                    MMA_BF16(d[mt][nt], ah[mt], bh[nt]);
                    MMA_BF16(d[mt][nt], ah[mt], bl[nt]);
                    MMA_BF16(d[mt][nt], al[mt], bh[nt]);
                }
        }
        __syncthreads();   // all warps done reading A/W smem

        if (phase == 0) {
            // ---- W2 hi/lo -> smem ----
            const uint32_t* wg = reinterpret_cast<const uint32_t*>(wimg);
            uint32_t* wh = reinterpret_cast<uint32_t*>(smem + SM_WHI);
            uint32_t* wl = reinterpret_cast<uint32_t*>(smem + SM_WLO);
#pragma unroll
            for (int i = 0; i < 32; i++) {
                int idx = tid + i * 256;
                int r = idx >> 6, c2 = idx & 63;
                wh[r * 68 + c2] = wg[OFF_W2HI + idx];
                wl[r * 68 + c2] = wg[OFF_W2LO + idx];
            }
            // ---- epilogue 1: z = relu(D + b1) -> bf16 hi/lo back into A smem ----
            const float* bs = bias_s[0];
#pragma unroll
            for (int mt = 0; mt < 2; mt++)
#pragma unroll
                for (int nt = 0; nt < 8; nt++) {
                    int r0 = wm + mt * 16 + (int)qr;
                    int c0 = wn + nt * 8 + (int)(qc * 2);
                    float v0 = fmaxf(d[mt][nt][0] + bs[c0],     0.f);
                    float v1 = fmaxf(d[mt][nt][1] + bs[c0 + 1], 0.f);
                    float v2 = fmaxf(d[mt][nt][2] + bs[c0],     0.f);
                    float v3 = fmaxf(d[mt][nt][3] + bs[c0 + 1], 0.f);
                    __nv_bfloat16 h0 = __float2bfloat16_rn(v0), h1 = __float2bfloat16_rn(v1);
                    __nv_bfloat16 h2 = __float2bfloat16_rn(v2), h3 = __float2bfloat16_rn(v3);
                    uint32_t i0 = (uint32_t)(r0 * 68 + c0 / 2);
                    uint32_t i1 = (uint32_t)((r0 + 8) * 68 + c0 / 2);
                    reinterpret_cast<uint32_t*>(smem + SM_AHI)[i0] =
                        pack2bf(__bfloat162float(h0), __bfloat162float(h1));
                    reinterpret_cast<uint32_t*>(smem + SM_AHI)[i1] =
                        pack2bf(__bfloat162float(h2), __bfloat162float(h3));
                    reinterpret_cast<uint32_t*>(smem + SM_ALO)[i0] =
                        pack2bf(v0 - __bfloat162float(h0), v1 - __bfloat162float(h1));
                    reinterpret_cast<uint32_t*>(smem + SM_ALO)[i1] =
                        pack2bf(v2 - __bfloat162float(h2), v3 - __bfloat162float(h3));
                }
            __syncthreads();
        } else {
            // ---- epilogue 2: out = relu(D + b2) -> gmem fp32 ----
            const float* bs = bias_s[1];
#pragma unroll
            for (int mt = 0; mt < 2; mt++)
#pragma unroll
                for (int nt = 0; nt < 8; nt++) {
                    int r0 = wm + mt * 16 + (int)qr;
                    int c0 = wn + nt * 8 + (int)(qc * 2);
                    if (r0 < maxr) {
                        float2 o;
                        o.x = fmaxf(d[mt][nt][0] + bs[c0],     0.f);
                        o.y = fmaxf(d[mt][nt][1] + bs[c0 + 1], 0.f);
                        *reinterpret_cast<float2*>(out + (size_t)(m0 + r0) * DIM + c0) = o;
                    }
                    if (r0 + 8 < maxr) {
                        float2 o;
                        o.x = fmaxf(d[mt][nt][2] + bs[c0],     0.f);
                        o.y = fmaxf(d[mt][nt][3] + bs[c0 + 1], 0.f);
                        *reinterpret_cast<float2*>(out + (size_t)(m0 + r0 + 8) * DIM + c0) = o;
                    }
                }
        }
    }
}

// ---------------------------------------------------------------------------
// Pooling: (sum_n h[n]@Wh per graph) / cnt
// ---------------------------------------------------------------------------
__global__ void pool_kernel(const float* __restrict__ h,
                            const int* __restrict__ batch,
                            const float* __restrict__ Wh,
                            float* __restrict__ gsum, int* __restrict__ gcnt) {
    int warp = (blockIdx.x * blockDim.x + threadIdx.x) >> 5;
    int lane = threadIdx.x & 31;
    if (warp >= NNODES) return;
    float4 v = reinterpret_cast<const float4*>(h + (size_t)warp * DIM)[lane];
    float4 w = reinterpret_cast<const float4*>(Wh)[lane];
    float s = v.x * w.x + v.y * w.y + v.z * w.z + v.w * w.w;
#pragma unroll
    for (int off = 16; off > 0; off >>= 1)
        s += __shfl_xor_sync(0xFFFFFFFF, s, off);
    if (lane == 0) {
        int g = batch[warp];
        atomicAdd(&gsum[g], s);
        atomicAdd(&gcnt[g], 1);
    }
}

__global__ void finalize_kernel(const float* __restrict__ gsum,
                                const int* __restrict__ gcnt,
                                const float* __restrict__ bh,
                                float* __restrict__ out) {
    int g = blockIdx.x * blockDim.x + threadIdx.x;
    if (g < NGRAPH) {
        float c = (float)gcnt[g];
        out[g] = gsum[g] / fmaxf(c, 1.0f) + bh[0];
    }
}

// ---------------------------------------------------------------------------
extern "C" void kernel_launch(void* const* d_in, const int* in_sizes, int n_in,
                              void* d_out, int out_size) {
    const float* x     = (const float*)d_in[0];
    const int*   ei    = (const int*)d_in[1];
    const int*   batch = (const int*)d_in[2];
    const float* W1s   = (const float*)d_in[3];
    const float* b1s   = (const float*)d_in[4];
    const float* W2s   = (const float*)d_in[5];
    const float* b2s   = (const float*)d_in[6];
    const float* Wh    = (const float*)d_in[7];
    const float* bh    = (const float*)d_in[8];
    float* out = (float*)d_out;

    float *h, *aggr, *gsum;
    int* gcnt;
    __nv_bfloat16* wimg;
    cudaGetSymbolAddress((void**)&h,    g_h);
    cudaGetSymbolAddress((void**)&aggr, g_aggr);
    cudaGetSymbolAddress((void**)&gsum, g_gsum);
    cudaGetSymbolAddress((void**)&gcnt, g_gcnt);
    cudaGetSymbolAddress((void**)&wimg, g_wimg);

    cudaFuncSetAttribute(gin_mlp_kernel,
                         cudaFuncAttributeMaxDynamicSharedMemorySize, SM_TOTAL);

    const int scatter_blocks = (NEDGES * 32 + 255) / 256;
    const int pool_blocks = (NNODES * 32 + 255) / 256;

    prep_w_kernel<<<(NLAYER * 2 * DIM * DIM + 255) / 256, 256>>>(W1s, W2s);

    const float* in = x;
    for (int l = 0; l < NLAYER; l++) {
        cudaMemsetAsync(aggr, 0, (size_t)NNODES * DIM * sizeof(float));
        scatter_kernel<<<scatter_blocks, 256>>>(ei, ei + NEDGES, in, aggr);
        gin_mlp_kernel<<<NTILES, 256, SM_TOTAL>>>(
            in, aggr, wimg + (size_t)l * 4 * DIM * DIM,
            b1s + (size_t)l * DIM, b2s + (size_t)l * DIM, h, NNODES);
        in = h;
    }

    cudaMemsetAsync(gsum, 0, NGRAPH * sizeof(float));
    cudaMemsetAsync(gcnt, 0, NGRAPH * sizeof(int));
    pool_kernel<<<pool_blocks, 256>>>(h, batch, Wh, gsum, gcnt);
    finalize_kernel<<<(NGRAPH + 255) / 256, 256>>>(gsum, gcnt, bh, out);
}

// round 14
// speedup vs baseline: 2.6512x; 1.4926x over previous
#include <cuda_runtime.h>
#include <cuda_bf16.h>
#include <cstdint>

#define NNODES 50000
#define NEDGES 800000
#define DIM    128
#define NLAYER 5
#define NGRAPH 1000
#define TILE_M 128
#define NTILES ((NNODES + TILE_M - 1) / TILE_M)

// ---------------------------------------------------------------------------
// Scratch (no allocation allowed)
// ---------------------------------------------------------------------------
__device__ float g_h[NNODES * DIM];
__device__ float g_z[NNODES * DIM];          // z = h + sum_neighbors(h), MLP input
__device__ __nv_bfloat16 g_wimg[NLAYER * 4 * DIM * DIM];  // W1hi,W1lo,W2hi,W2lo per layer (W^T)
__device__ float g_gsum[NGRAPH];
__device__ int   g_gcnt[NGRAPH];
// CSR scratch
__device__ int g_deg[NNODES];
__device__ int g_rs[NNODES + 1];
__device__ int g_pos[NNODES];
__device__ int g_csr[NEDGES];

// ---------------------------------------------------------------------------
// helpers
// ---------------------------------------------------------------------------
__device__ __forceinline__ uint32_t smem_u32(const void* p) {
    uint32_t a;
    asm("{ .reg .u64 t; cvta.to.shared.u64 t, %1; cvt.u32.u64 %0, t; }" : "=r"(a) : "l"(p));
    return a;
}
__device__ __forceinline__ uint32_t pack2bf(float a, float b) {
    __nv_bfloat162 t = __floats2bfloat162_rn(a, b);
    return *reinterpret_cast<uint32_t*>(&t);
}

#define LDSM_X4(r0, r1, r2, r3, addr) \
    asm volatile("ldmatrix.sync.aligned.m8n8.x4.shared.b16 {%0,%1,%2,%3}, [%4];" \
                 : "=r"(r0), "=r"(r1), "=r"(r2), "=r"(r3) : "r"(addr))

#define MMA_BF16(d, a, b) \
    asm volatile("mma.sync.aligned.m16n8k16.row.col.f32.bf16.bf16.f32 " \
                 "{%0,%1,%2,%3}, {%4,%5,%6,%7}, {%8,%9}, {%0,%1,%2,%3};" \
                 : "+f"((d)[0]), "+f"((d)[1]), "+f"((d)[2]), "+f"((d)[3]) \
                 : "r"((a)[0]), "r"((a)[1]), "r"((a)[2]), "r"((a)[3]), \
                   "r"((b)[0]), "r"((b)[1]))

#define WIMG_U32 8192
#define OFF_W1HI 0
#define OFF_W1LO (1 * WIMG_U32)
#define OFF_W2HI (2 * WIMG_U32)
#define OFF_W2LO (3 * WIMG_U32)

// ---------------------------------------------------------------------------
// Weight prep: fp32 [L][K][N] -> transposed bf16 hi/lo images [n][k]
// ---------------------------------------------------------------------------
__global__ void prep_w_kernel(const float* __restrict__ W1s, const float* __restrict__ W2s) {
    int idx = blockIdx.x * blockDim.x + threadIdx.x;
    if (idx >= NLAYER * 2 * DIM * DIM) return;
    int l = idx / (2 * DIM * DIM);
    int rem = idx % (2 * DIM * DIM);
    int m = rem / (DIM * DIM);
    int kn = rem % (DIM * DIM);
    int k = kn / DIM, n = kn % DIM;
    float w = (m == 0 ? W1s : W2s)[(size_t)l * DIM * DIM + k * DIM + n];
    __nv_bfloat16 hi = __float2bfloat16_rn(w);
    __nv_bfloat16 lo = __float2bfloat16_rn(w - __bfloat162float(hi));
    __nv_bfloat16* base = g_wimg + (size_t)(l * 4 + m * 2) * DIM * DIM;
    base[n * DIM + k] = hi;
    base[DIM * DIM + n * DIM + k] = lo;
}

// ---------------------------------------------------------------------------
// CSR build: histogram -> scan -> fill (per launch; reused for all 5 layers)
// ---------------------------------------------------------------------------
__global__ void hist_kernel(const int* __restrict__ dst) {
    int e = blockIdx.x * blockDim.x + threadIdx.x;
    if (e < NEDGES) atomicAdd(&g_deg[dst[e]], 1);
}

#define SCAN_T 1024
#define CHUNK ((NNODES + SCAN_T - 1) / SCAN_T)
__global__ __launch_bounds__(SCAN_T) void scan_kernel() {
    int t = threadIdx.x;
    int base = t * CHUNK;
    int sum = 0;
#pragma unroll
    for (int i = 0; i < CHUNK; i++) {
        int idx = base + i;
        if (idx < NNODES) sum += g_deg[idx];
    }
    __shared__ int wsum[32];
    int lane = t & 31, w = t >> 5;
    int v = sum;
#pragma unroll
    for (int o = 1; o < 32; o <<= 1) {
        int u = __shfl_up_sync(0xFFFFFFFF, v, o);
        if (lane >= o) v += u;
    }
    if (lane == 31) wsum[w] = v;
    __syncthreads();
    if (w == 0) {
        int x = wsum[lane];
#pragma unroll
        for (int o = 1; o < 32; o <<= 1) {
            int u = __shfl_up_sync(0xFFFFFFFF, x, o);
            if (lane >= o) x += u;
        }
        wsum[lane] = x;
    }
    __syncthreads();
    int excl = v - sum + (w > 0 ? wsum[w - 1] : 0);
    int run = excl;
#pragma unroll
    for (int i = 0; i < CHUNK; i++) {
        int idx = base + i;
        if (idx < NNODES) { g_rs[idx] = run; run += g_deg[idx]; }
    }
    if (t == SCAN_T - 1) g_rs[NNODES] = run;
}

__global__ void fill_kernel(const int* __restrict__ src, const int* __restrict__ dst) {
    int e = blockIdx.x * blockDim.x + threadIdx.x;
    if (e >= NEDGES) return;
    int d = dst[e];
    int p = atomicAdd(&g_pos[d], 1);
    g_csr[g_rs[d] + p] = src[e];
}

// ---------------------------------------------------------------------------
// Gather aggregation: z[n] = h[n] + sum_{s in nbrs(n)} h[s]. One warp/node.
// ---------------------------------------------------------------------------
__global__ void gather_kernel(const float* __restrict__ h, float* __restrict__ z) {
    int warp = (blockIdx.x * blockDim.x + threadIdx.x) >> 5;
    int lane = threadIdx.x & 31;
    if (warp >= NNODES) return;
    int beg = g_rs[warp], end = g_rs[warp + 1];
    const float4* h4 = reinterpret_cast<const float4*>(h);
    float4 acc = h4[(size_t)warp * 32 + lane];
    for (int cb = beg; cb < end; cb += 32) {
        int e = cb + lane;
        int sidx = (e < end) ? g_csr[e] : 0;
        int cnt = min(32, end - cb);
        for (int i = 0; i < cnt; i++) {
            int s = __shfl_sync(0xFFFFFFFF, sidx, i);
            float4 v = h4[(size_t)s * 32 + lane];
            acc.x += v.x; acc.y += v.y; acc.z += v.z; acc.w += v.w;
        }
    }
    reinterpret_cast<float4*>(z)[(size_t)warp * 32 + lane] = acc;
}

// ---------------------------------------------------------------------------
// Fused GIN MLP: out = relu(relu(z @ W1 + b1) @ W2 + b2)
// One CTA per 128 rows; warp mma.sync bf16 hi/lo split; K=128 resident.
// ---------------------------------------------------------------------------
#define ASTRIDE 136
#define TILE_BYTES (128 * ASTRIDE * 2)
#define SM_AHI 0
#define SM_ALO (SM_AHI + TILE_BYTES)
#define SM_WHI (SM_ALO + TILE_BYTES)
#define SM_WLO (SM_WHI + TILE_BYTES)
#define SM_B1  (SM_WLO + TILE_BYTES)
#define SM_B2  (SM_B1 + 512)
#define SM_TOTAL (SM_B2 + 512)

__global__ __launch_bounds__(256, 1) void gin_mlp_kernel(
    const float* __restrict__ zin,
    const __nv_bfloat16* __restrict__ wimg,
    const float* __restrict__ b1, const float* __restrict__ b2,
    float* __restrict__ out, int M)
{
    extern __shared__ char smem[];
    uint32_t sb = smem_u32(smem);
    int tid = threadIdx.x;
    int wid = tid >> 5;
    int lane = tid & 31;
    int m0 = blockIdx.x * TILE_M;
    int maxr = M - m0;

    if (tid < DIM) {
        *reinterpret_cast<float*>(smem + SM_B1 + tid * 4) = b1[tid];
        *reinterpret_cast<float*>(smem + SM_B2 + tid * 4) = b2[tid];
    }

    // ---- W1 hi/lo -> smem ----
    {
        const uint32_t* wg = reinterpret_cast<const uint32_t*>(wimg);
        uint32_t* wh = reinterpret_cast<uint32_t*>(smem + SM_WHI);
        uint32_t* wl = reinterpret_cast<uint32_t*>(smem + SM_WLO);
#pragma unroll
        for (int i = 0; i < 32; i++) {
            int idx = tid + i * 256;
            int r = idx >> 6, c2 = idx & 63;
            wh[r * 68 + c2] = wg[OFF_W1HI + idx];
            wl[r * 68 + c2] = wg[OFF_W1LO + idx];
        }
    }

    // ---- A tile: z -> bf16 hi/lo, padded smem ----
    {
        const float4* in4 = reinterpret_cast<const float4*>(zin + (size_t)m0 * DIM);
#pragma unroll
        for (int i = 0; i < 16; i++) {
            int f = tid + i * 256;
            int r = f >> 5, c4 = f & 31;
            float4 a = make_float4(0.f, 0.f, 0.f, 0.f);
            if (r < maxr) a = in4[f];
            __nv_bfloat16 h0 = __float2bfloat16_rn(a.x), h1 = __float2bfloat16_rn(a.y);
            __nv_bfloat16 h2 = __float2bfloat16_rn(a.z), h3 = __float2bfloat16_rn(a.w);
            uint32_t u32i = (uint32_t)(r * 68 + c4 * 2);
            reinterpret_cast<uint2*>(smem + SM_AHI)[u32i >> 1] =
                make_uint2(pack2bf(__bfloat162float(h0), __bfloat162float(h1)),
                           pack2bf(__bfloat162float(h2), __bfloat162float(h3)));
            reinterpret_cast<uint2*>(smem + SM_ALO)[u32i >> 1] =
                make_uint2(pack2bf(a.x - __bfloat162float(h0), a.y - __bfloat162float(h1)),
                           pack2bf(a.z - __bfloat162float(h2), a.w - __bfloat162float(h3)));
        }
    }
    __syncthreads();

    int wm = (wid & 3) * 32;
    int wn = (wid >> 2) * 64;
    uint32_t a_off = (uint32_t)(((lane & 15) * ASTRIDE) * 2 + (lane >> 4) * 16);
    uint32_t b_off = (uint32_t)((((lane >> 4) * 8 + (lane & 7)) * ASTRIDE) * 2 + ((lane >> 3) & 1) * 16);

    float d[2][8][4];
    uint32_t qr = lane >> 2, qc = lane & 3;
    const float* bias_s[2] = { reinterpret_cast<const float*>(smem + SM_B1),
                               reinterpret_cast<const float*>(smem + SM_B2) };

#pragma unroll 1
    for (int phase = 0; phase < 2; phase++) {
#pragma unroll
        for (int mt = 0; mt < 2; mt++)
#pragma unroll
            for (int nt = 0; nt < 8; nt++)
#pragma unroll
                for (int r = 0; r < 4; r++) d[mt][nt][r] = 0.f;

#pragma unroll
        for (int ks = 0; ks < 8; ks++) {
            uint32_t kbyte = (uint32_t)(ks * 32);
            uint32_t ah[2][4], al[2][4], bh[8][2], bl[8][2];
#pragma unroll
            for (int mt = 0; mt < 2; mt++) {
                uint32_t row = (uint32_t)((wm + mt * 16) * ASTRIDE * 2);
                LDSM_X4(ah[mt][0], ah[mt][1], ah[mt][2], ah[mt][3], sb + SM_AHI + row + a_off + kbyte);
                LDSM_X4(al[mt][0], al[mt][1], al[mt][2], al[mt][3], sb + SM_ALO + row + a_off + kbyte);
            }
#pragma unroll
            for (int np = 0; np < 4; np++) {
                uint32_t row = (uint32_t)((wn + np * 16) * ASTRIDE * 2);
                LDSM_X4(bh[np*2][0], bh[np*2][1], bh[np*2+1][0], bh[np*2+1][1], sb + SM_WHI + row + b_off + kbyte);
                LDSM_X4(bl[np*2][0], bl[np*2][1], bl[np*2+1][0], bl[np*2+1][1], sb + SM_WLO + row + b_off + kbyte);
            }
#pragma unroll
            for (int mt = 0; mt < 2; mt++)
#pragma unroll
                for (int nt = 0; nt < 8; nt++) {
                    MMA_BF16(d[mt][nt], ah[mt], bh[nt]);
                    MMA_BF16(d[mt][nt], ah[mt], bl[nt]);
                    MMA_BF16(d[mt][nt], al[mt], bh[nt]);
                }
        }
        __syncthreads();

        if (phase == 0) {
            const uint32_t* wg = reinterpret_cast<const uint32_t*>(wimg);
            uint32_t* wh = reinterpret_cast<uint32_t*>(smem + SM_WHI);
            uint32_t* wl = reinterpret_cast<uint32_t*>(smem + SM_WLO);
#pragma unroll
            for (int i = 0; i < 32; i++) {
                int idx = tid + i * 256;
                int r = idx >> 6, c2 = idx & 63;
                wh[r * 68 + c2] = wg[OFF_W2HI + idx];
                wl[r * 68 + c2] = wg[OFF_W2LO + idx];
            }
            const float* bs = bias_s[0];
#pragma unroll
            for (int mt = 0; mt < 2; mt++)
#pragma unroll
                for (int nt = 0; nt < 8; nt++) {
                    int r0 = wm + mt * 16 + (int)qr;
                    int c0 = wn + nt * 8 + (int)(qc * 2);
                    float v0 = fmaxf(d[mt][nt][0] + bs[c0],     0.f);
                    float v1 = fmaxf(d[mt][nt][1] + bs[c0 + 1], 0.f);
                    float v2 = fmaxf(d[mt][nt][2] + bs[c0],     0.f);
                    float v3 = fmaxf(d[mt][nt][3] + bs[c0 + 1], 0.f);
                    __nv_bfloat16 h0 = __float2bfloat16_rn(v0), h1 = __float2bfloat16_rn(v1);
                    __nv_bfloat16 h2 = __float2bfloat16_rn(v2), h3 = __float2bfloat16_rn(v3);
                    uint32_t i0 = (uint32_t)(r0 * 68 + c0 / 2);
                    uint32_t i1 = (uint32_t)((r0 + 8) * 68 + c0 / 2);
                    reinterpret_cast<uint32_t*>(smem + SM_AHI)[i0] =
                        pack2bf(__bfloat162float(h0), __bfloat162float(h1));
                    reinterpret_cast<uint32_t*>(smem + SM_AHI)[i1] =
                        pack2bf(__bfloat162float(h2), __bfloat162float(h3));
                    reinterpret_cast<uint32_t*>(smem + SM_ALO)[i0] =
                        pack2bf(v0 - __bfloat162float(h0), v1 - __bfloat162float(h1));
                    reinterpret_cast<uint32_t*>(smem + SM_ALO)[i1] =
                        pack2bf(v2 - __bfloat162float(h2), v3 - __bfloat162float(h3));
                }
            __syncthreads();
        } else {
            const float* bs = bias_s[1];
#pragma unroll
            for (int mt = 0; mt < 2; mt++)
#pragma unroll
                for (int nt = 0; nt < 8; nt++) {
                    int r0 = wm + mt * 16 + (int)qr;
                    int c0 = wn + nt * 8 + (int)(qc * 2);
                    if (r0 < maxr) {
                        float2 o;
                        o.x = fmaxf(d[mt][nt][0] + bs[c0],     0.f);
                        o.y = fmaxf(d[mt][nt][1] + bs[c0 + 1], 0.f);
                        *reinterpret_cast<float2*>(out + (size_t)(m0 + r0) * DIM + c0) = o;
                    }
                    if (r0 + 8 < maxr) {
                        float2 o;
                        o.x = fmaxf(d[mt][nt][2] + bs[c0],     0.f);
                        o.y = fmaxf(d[mt][nt][3] + bs[c0 + 1], 0.f);
                        *reinterpret_cast<float2*>(out + (size_t)(m0 + r0 + 8) * DIM + c0) = o;
                    }
                }
        }
    }
}

// ---------------------------------------------------------------------------
// Pooling: (sum_n h[n]@Wh per graph) / cnt
// ---------------------------------------------------------------------------
__global__ void pool_kernel(const float* __restrict__ h,
                            const int* __restrict__ batch,
                            const float* __restrict__ Wh,
                            float* __restrict__ gsum, int* __restrict__ gcnt) {
    int warp = (blockIdx.x * blockDim.x + threadIdx.x) >> 5;
    int lane = threadIdx.x & 31;
    if (warp >= NNODES) return;
    float4 v = reinterpret_cast<const float4*>(h + (size_t)warp * DIM)[lane];
    float4 w = reinterpret_cast<const float4*>(Wh)[lane];
    float s = v.x * w.x + v.y * w.y + v.z * w.z + v.w * w.w;
#pragma unroll
    for (int off = 16; off > 0; off >>= 1)
        s += __shfl_xor_sync(0xFFFFFFFF, s, off);
    if (lane == 0) {
        int g = batch[warp];
        atomicAdd(&gsum[g], s);
        atomicAdd(&gcnt[g], 1);
    }
}

__global__ void finalize_kernel(const float* __restrict__ gsum,
                                const int* __restrict__ gcnt,
                                const float* __restrict__ bh,
                                float* __restrict__ out) {
    int g = blockIdx.x * blockDim.x + threadIdx.x;
    if (g < NGRAPH) {
        float c = (float)gcnt[g];
        out[g] = gsum[g] / fmaxf(c, 1.0f) + bh[0];
    }
}

// ---------------------------------------------------------------------------
extern "C" void kernel_launch(void* const* d_in, const int* in_sizes, int n_in,
                              void* d_out, int out_size) {
    const float* x     = (const float*)d_in[0];
    const int*   ei    = (const int*)d_in[1];
    const int*   batch = (const int*)d_in[2];
    const float* W1s   = (const float*)d_in[3];
    const float* b1s   = (const float*)d_in[4];
    const float* W2s   = (const float*)d_in[5];
    const float* b2s   = (const float*)d_in[6];
    const float* Wh    = (const float*)d_in[7];
    const float* bh    = (const float*)d_in[8];
    float* out = (float*)d_out;

    float *h, *z, *gsum;
    int *gcnt, *deg, *pos;
    __nv_bfloat16* wimg;
    cudaGetSymbolAddress((void**)&h,    g_h);
    cudaGetSymbolAddress((void**)&z,    g_z);
    cudaGetSymbolAddress((void**)&gsum, g_gsum);
    cudaGetSymbolAddress((void**)&gcnt, g_gcnt);
    cudaGetSymbolAddress((void**)&wimg, g_wimg);
    cudaGetSymbolAddress((void**)&deg,  g_deg);
    cudaGetSymbolAddress((void**)&pos,  g_pos);

    cudaFuncSetAttribute(gin_mlp_kernel,
                         cudaFuncAttributeMaxDynamicSharedMemorySize, SM_TOTAL);

    const int edge_blocks = (NEDGES + 255) / 256;
    const int node_warp_blocks = (NNODES * 32 + 255) / 256;

    // ---- CSR build (once; reused for all 5 layers) ----
    cudaMemsetAsync(deg, 0, NNODES * sizeof(int));
    cudaMemsetAsync(pos, 0, NNODES * sizeof(int));
    hist_kernel<<<edge_blocks, 256>>>(ei + NEDGES);
    scan_kernel<<<1, SCAN_T>>>();
    fill_kernel<<<edge_blocks, 256>>>(ei, ei + NEDGES);

    prep_w_kernel<<<(NLAYER * 2 * DIM * DIM + 255) / 256, 256>>>(W1s, W2s);

    const float* in = x;
    for (int l = 0; l < NLAYER; l++) {
        gather_kernel<<<node_warp_blocks, 256>>>(in, z);
        gin_mlp_kernel<<<NTILES, 256, SM_TOTAL>>>(
            z, wimg + (size_t)l * 4 * DIM * DIM,
            b1s + (size_t)l * DIM, b2s + (size_t)l * DIM, h, NNODES);
        in = h;
    }

    cudaMemsetAsync(gsum, 0, NGRAPH * sizeof(float));
    cudaMemsetAsync(gcnt, 0, NGRAPH * sizeof(int));
    pool_kernel<<<node_warp_blocks, 256>>>(h, batch, Wh, gsum, gcnt);
    finalize_kernel<<<(NGRAPH + 255) / 256, 256>>>(gsum, gcnt, bh, out);
}